// round 5
// baseline (speedup 1.0000x reference)
#include <cuda_runtime.h>
#include <cuda_bf16.h>
#include <cstdint>

// ---------------------------------------------------------------------------
// PCDKNNGroupEncoder: FPS -> KNN group -> MLP(6->128 bn relu ->256) ->
//   concat(groupmax, f2) -> 512->512 bn relu -> 384 -> groupmax
// B=32, N=16384, G=64, K=32  => 2048 groups, 65536 MLP rows
// ---------------------------------------------------------------------------

#define NPTS 16384
#define NGRP 64
#define KNN  32

// -------------------- scratch (device globals; no allocation) --------------
__device__ float g_x  [65536 * 6];                 // grouped features
__device__ float g_f1 [(size_t)65536 * 128];       // 32 MB
__device__ float g_f2 [(size_t)65536 * 256];       // 64 MB
__device__ float g_f3 [(size_t)65536 * 512];       // 128 MB
__device__ float g_fg [2048 * 256];                // group max of f2
__device__ float g_fgw[2048 * 512];                // fg @ w3[:256] + b3
__device__ int   g_cidx[2048];
__device__ float g_s1[128], g_h1[128], g_s2[512], g_h2[512];

// -------------------- helpers ----------------------------------------------
__device__ __forceinline__ unsigned long long wmax64(unsigned long long v) {
#pragma unroll
    for (int o = 16; o; o >>= 1) {
        unsigned long long u = __shfl_xor_sync(0xffffffffu, v, o);
        v = v > u ? v : u;
    }
    return v;
}

__device__ __forceinline__ float dist2(float x, float y, float z,
                                       float cx, float cy, float cz) {
    // mul/add (no fma contraction) to mirror XLA elementwise lowering
    float dx = __fadd_rn(x, -cx);
    float dy = __fadd_rn(y, -cy);
    float dz = __fadd_rn(z, -cz);
    return __fadd_rn(__fadd_rn(__fmul_rn(dx, dx), __fmul_rn(dy, dy)),
                     __fmul_rn(dz, dz));
}

// -------------------- bn precompute ----------------------------------------
__global__ void bnprep_kernel(const float* __restrict__ g1, const float* __restrict__ be1,
                              const float* __restrict__ m1, const float* __restrict__ v1,
                              const float* __restrict__ g2, const float* __restrict__ be2,
                              const float* __restrict__ m2, const float* __restrict__ v2,
                              float* __restrict__ s1, float* __restrict__ h1,
                              float* __restrict__ s2, float* __restrict__ h2) {
    int i = threadIdx.x;
    if (i < 128) { float s = g1[i] * rsqrtf(v1[i] + 1e-5f); s1[i] = s; h1[i] = be1[i] - m1[i] * s; }
    if (i < 512) { float s = g2[i] * rsqrtf(v2[i] + 1e-5f); s2[i] = s; h2[i] = be2[i] - m2[i] * s; }
}

// -------------------- farthest point sampling ------------------------------
// one block per batch; 1024 threads, 16 points/thread; dists in registers.
// argmax tie-break: lowest index (matches jnp.argmax) via (dist_bits<<32)|(16383-p)
__global__ void __launch_bounds__(1024) fps_kernel(const float* __restrict__ pcd,
                                                   int* __restrict__ cidx) {
    int b = blockIdx.x;
    const float* __restrict__ px = pcd + (size_t)b * 6 * NPTS;
    const float* __restrict__ py = px + NPTS;
    const float* __restrict__ pz = px + 2 * NPTS;
    __shared__ unsigned long long red[32];
    __shared__ int scur;
    int tid = threadIdx.x, lane = tid & 31, wid = tid >> 5;

    float dl[16];
#pragma unroll
    for (int j = 0; j < 16; j++) dl[j] = 1e10f;

    int cur = 0;
    for (int it = 0; it < NGRP; it++) {
        if (tid == 0) cidx[b * NGRP + it] = cur;
        float cx = __ldg(px + cur), cy = __ldg(py + cur), cz = __ldg(pz + cur);
        unsigned long long best = 0;
#pragma unroll
        for (int j = 0; j < 16; j++) {
            int p = tid + j * 1024;
            float d2 = dist2(__ldg(px + p), __ldg(py + p), __ldg(pz + p), cx, cy, cz);
            float dn = fminf(dl[j], d2);
            dl[j] = dn;
            unsigned long long key =
                ((unsigned long long)__float_as_uint(dn) << 32) | (unsigned)(16383 - p);
            best = best > key ? best : key;
        }
        best = wmax64(best);
        if (lane == 0) red[wid] = best;
        __syncthreads();
        if (wid == 0) {
            unsigned long long v = wmax64(red[lane]);
            if (lane == 0) scur = 16383 - (int)(v & 0xffffffffu);
        }
        __syncthreads();
        cur = scur;
    }
}

// -------------------- KNN + gather + center subtraction --------------------
// one warp per (batch,group). Warp-select top-32 smallest (d2, idx) keys:
// each lane holds one candidate; thr = current warp max; insert on qualify.
__global__ void __launch_bounds__(256) knn_kernel(const float* __restrict__ pcd,
                                                  const int* __restrict__ cidx,
                                                  float* __restrict__ xf) {
    int gw = (int)((blockIdx.x * 256 + threadIdx.x) >> 5);   // 0..2047
    int lane = threadIdx.x & 31;
    int b = gw >> 6;
    const float* __restrict__ px = pcd + (size_t)b * 6 * NPTS;
    const float* __restrict__ py = px + NPTS;
    const float* __restrict__ pz = py + NPTS;
    const float* __restrict__ p3 = pz + NPTS;
    const float* __restrict__ p4 = p3 + NPTS;
    const float* __restrict__ p5 = p4 + NPTS;

    int ci = cidx[gw];
    float cx = __ldg(px + ci), cy = __ldg(py + ci), cz = __ldg(pz + ci);

    float d0 = dist2(__ldg(px + lane), __ldg(py + lane), __ldg(pz + lane), cx, cy, cz);
    unsigned long long held = ((unsigned long long)__float_as_uint(d0) << 32) | (unsigned)lane;
    unsigned long long thr = wmax64(held);

    for (int base = 32; base < NPTS; base += 32) {
        int n = base + lane;
        float d2 = dist2(__ldg(px + n), __ldg(py + n), __ldg(pz + n), cx, cy, cz);
        unsigned long long key = ((unsigned long long)__float_as_uint(d2) << 32) | (unsigned)n;
        unsigned qm = __ballot_sync(0xffffffffu, key < thr);
        while (qm) {
            int src = __ffs(qm) - 1;
            qm &= qm - 1;
            unsigned long long cand = __shfl_sync(0xffffffffu, key, src);
            if (cand < thr) {                       // uniform branch
                unsigned rm = __ballot_sync(0xffffffffu, held == thr);
                if (lane == __ffs(rm) - 1) held = cand;
                thr = wmax64(held);
            }
        }
    }
    int n = (int)(held & 0xffffffffu);
    size_t row = (size_t)gw * KNN + lane;
    float* o = xf + row * 6;
    o[0] = __fadd_rn(__ldg(px + n), -cx);
    o[1] = __fadd_rn(__ldg(py + n), -cy);
    o[2] = __fadd_rn(__ldg(pz + n), -cz);
    o[3] = __ldg(p3 + n);
    o[4] = __ldg(p4 + n);
    o[5] = __ldg(p5 + n);
}

// -------------------- layer1: 6 -> 128 + bn1 + relu ------------------------
// block handles 64 rows; outputs column-contiguous for coalesced stores.
__global__ void __launch_bounds__(256) layer1_kernel(const float* __restrict__ xf,
                                                     const float* __restrict__ w1,
                                                     const float* __restrict__ b1,
                                                     const float* __restrict__ s1,
                                                     const float* __restrict__ h1,
                                                     float* __restrict__ f1) {
    __shared__ float ws[768];
    __shared__ float bs[128], sc[128], sh[128];
    __shared__ float xs[384];
    int tid = threadIdx.x;
    size_t rowBase = (size_t)blockIdx.x * 64;
    for (int i = tid; i < 768; i += 256) ws[i] = w1[i];
    if (tid < 128) { bs[tid] = b1[tid]; sc[tid] = s1[tid]; sh[tid] = h1[tid]; }
    for (int i = tid; i < 384; i += 256) xs[i] = xf[rowBase * 6 + i];
    __syncthreads();
#pragma unroll 4
    for (int i = 0; i < 32; i++) {
        int o = i * 256 + tid;
        int col = o & 127, r = o >> 7;
        float acc = bs[col];
#pragma unroll
        for (int j = 0; j < 6; j++) acc = fmaf(xs[r * 6 + j], ws[j * 128 + col], acc);
        float v = fmaf(acc, sc[col], sh[col]);
        f1[(rowBase + r) * 128 + col] = fmaxf(v, 0.f);
    }
}

// -------------------- generic 128x128x16 fp32 GEMM, fused epilogues --------
// EPI 0: C = acc + bias
// EPI 1: C = acc + bias, aux[group][col] = max over 32-row groups (fg)
// EPI 2: C = relu((acc + fgw[row>>5][col]) * s2[col] + h2[col])   (aux = fgw in)
// EPI 3: aux[group][col] = max over 32-row groups of (acc + bias); no C write
template <int EPI>
__global__ void __launch_bounds__(256) sgemm(const float* __restrict__ A,
                                             const float* __restrict__ Bm,
                                             float* __restrict__ C,
                                             float* __restrict__ aux,
                                             const float* __restrict__ bias,
                                             const float* __restrict__ scale,
                                             const float* __restrict__ shift,
                                             int M, int N, int K, int auxN) {
    __shared__ float As[2][16][132];
    __shared__ float Bs[2][16][128];
    __shared__ float smax[16 * 128];

    int tid = threadIdx.x;
    int tx = tid & 15, ty = tid >> 4;
    int mBase = blockIdx.y << 7, nBase = blockIdx.x << 7;

    int aK = tid & 15, aM = tid >> 4;          // A tile: rows aM + e*16, col aK
    int bN = (tid & 31) << 2, bK = tid >> 5;   // B tile: rows bK + e*8, cols bN..bN+3

    const float* Ap = A + (size_t)(mBase + aM) * K + aK;
    const float* Bp = Bm + (size_t)bK * N + nBase + bN;

    float acc[8][8];
#pragma unroll
    for (int i = 0; i < 8; i++)
#pragma unroll
        for (int j = 0; j < 8; j++) acc[i][j] = 0.f;

    float ar[8];
    float4 br[2];
    int nt = K >> 4;

#pragma unroll
    for (int e = 0; e < 8; e++) ar[e] = Ap[(size_t)(e * 16) * K];
#pragma unroll
    for (int e = 0; e < 2; e++) br[e] = *(const float4*)(Bp + (size_t)(e * 8) * N);
#pragma unroll
    for (int e = 0; e < 8; e++) As[0][aK][aM + e * 16] = ar[e];
#pragma unroll
    for (int e = 0; e < 2; e++) *(float4*)&Bs[0][bK + e * 8][bN] = br[e];
    __syncthreads();

    for (int t = 0; t < nt; t++) {
        int buf = t & 1;
        if (t + 1 < nt) {
            int kOff = (t + 1) << 4;
#pragma unroll
            for (int e = 0; e < 8; e++) ar[e] = Ap[(size_t)(e * 16) * K + kOff];
#pragma unroll
            for (int e = 0; e < 2; e++)
                br[e] = *(const float4*)(Bp + (size_t)(kOff + e * 8) * N);
        }
#pragma unroll
        for (int kk = 0; kk < 16; kk++) {
            float a[8], bb[8];
            *(float4*)&a[0]  = *(const float4*)&As[buf][kk][ty * 8];
            *(float4*)&a[4]  = *(const float4*)&As[buf][kk][ty * 8 + 4];
            *(float4*)&bb[0] = *(const float4*)&Bs[buf][kk][tx * 8];
            *(float4*)&bb[4] = *(const float4*)&Bs[buf][kk][tx * 8 + 4];
#pragma unroll
            for (int i = 0; i < 8; i++)
#pragma unroll
                for (int j = 0; j < 8; j++) acc[i][j] = fmaf(a[i], bb[j], acc[i][j]);
        }
        if (t + 1 < nt) {
            int nb = buf ^ 1;
#pragma unroll
            for (int e = 0; e < 8; e++) As[nb][aK][aM + e * 16] = ar[e];
#pragma unroll
            for (int e = 0; e < 2; e++) *(float4*)&Bs[nb][bK + e * 8][bN] = br[e];
            __syncthreads();
        }
    }

    int colBase = nBase + tx * 8;

    if (EPI == 2) {
        int grow = (mBase + ty * 8) >> 5;   // constant per thread (8 | 32)
        float fw[8], sc[8], sh[8];
#pragma unroll
        for (int j = 0; j < 8; j++) {
            int c = colBase + j;
            fw[j] = __ldg(aux + (size_t)grow * N + c);
            sc[j] = __ldg(scale + c);
            sh[j] = __ldg(shift + c);
        }
#pragma unroll
        for (int i = 0; i < 8; i++) {
            float out[8];
#pragma unroll
            for (int j = 0; j < 8; j++) {
                float v = acc[i][j] + fw[j];
                v = fmaf(v, sc[j], sh[j]);
                out[j] = fmaxf(v, 0.f);
            }
            float* cp = C + (size_t)(mBase + ty * 8 + i) * N + colBase;
            *(float4*)cp = *(float4*)&out[0];
            *(float4*)(cp + 4) = *(float4*)&out[4];
        }
    } else {
        float bb8[8];
#pragma unroll
        for (int j = 0; j < 8; j++) bb8[j] = __ldg(bias + colBase + j);
#pragma unroll
        for (int i = 0; i < 8; i++)
#pragma unroll
            for (int j = 0; j < 8; j++) acc[i][j] += bb8[j];

        if (EPI == 0 || EPI == 1) {
#pragma unroll
            for (int i = 0; i < 8; i++) {
                float* cp = C + (size_t)(mBase + ty * 8 + i) * N + colBase;
                *(float4*)cp = *(float4*)&acc[i][0];
                *(float4*)(cp + 4) = *(float4*)&acc[i][4];
            }
        }
        if (EPI == 1 || EPI == 3) {
            float mx[8];
#pragma unroll
            for (int j = 0; j < 8; j++) {
                float v = acc[0][j];
#pragma unroll
                for (int i = 1; i < 8; i++) v = fmaxf(v, acc[i][j]);
                mx[j] = v;
            }
#pragma unroll
            for (int j = 0; j < 8; j++) smax[ty * 128 + tx * 8 + j] = mx[j];
            __syncthreads();
            int gBase = mBase >> 5;
            for (int o = tid; o < 512; o += 256) {
                int g = o >> 7, c = o & 127;
                const float* s = &smax[(g * 4) * 128 + c];
                float v = fmaxf(fmaxf(s[0], s[128]), fmaxf(s[256], s[384]));
                aux[(size_t)(gBase + g) * auxN + nBase + c] = v;
            }
        }
    }
}

// ---------------------------------------------------------------------------
extern "C" void kernel_launch(void* const* d_in, const int* in_sizes, int n_in,
                              void* d_out, int out_size) {
    (void)in_sizes; (void)n_in; (void)out_size;
    const float* pcd = (const float*)d_in[0];
    // d_in[1] = pcd_mask (unused)
    const float* w1  = (const float*)d_in[2];
    const float* b1  = (const float*)d_in[3];
    const float* g1  = (const float*)d_in[4];
    const float* be1 = (const float*)d_in[5];
    const float* m1  = (const float*)d_in[6];
    const float* v1  = (const float*)d_in[7];
    const float* w2  = (const float*)d_in[8];
    const float* b2  = (const float*)d_in[9];
    const float* w3  = (const float*)d_in[10];
    const float* b3  = (const float*)d_in[11];
    const float* g2  = (const float*)d_in[12];
    const float* be2 = (const float*)d_in[13];
    const float* m2  = (const float*)d_in[14];
    const float* v2  = (const float*)d_in[15];
    const float* w4  = (const float*)d_in[16];
    const float* b4  = (const float*)d_in[17];

    float *xf, *f1, *f2, *f3, *fg, *fgw, *s1, *h1, *s2, *h2;
    int* ci;
    cudaGetSymbolAddress((void**)&xf,  g_x);
    cudaGetSymbolAddress((void**)&f1,  g_f1);
    cudaGetSymbolAddress((void**)&f2,  g_f2);
    cudaGetSymbolAddress((void**)&f3,  g_f3);
    cudaGetSymbolAddress((void**)&fg,  g_fg);
    cudaGetSymbolAddress((void**)&fgw, g_fgw);
    cudaGetSymbolAddress((void**)&ci,  g_cidx);
    cudaGetSymbolAddress((void**)&s1,  g_s1);
    cudaGetSymbolAddress((void**)&h1,  g_h1);
    cudaGetSymbolAddress((void**)&s2,  g_s2);
    cudaGetSymbolAddress((void**)&h2,  g_h2);

    bnprep_kernel<<<1, 512>>>(g1, be1, m1, v1, g2, be2, m2, v2, s1, h1, s2, h2);
    fps_kernel<<<32, 1024>>>(pcd, ci);
    knn_kernel<<<256, 256>>>(pcd, ci, xf);
    layer1_kernel<<<1024, 256>>>(xf, w1, b1, s1, h1, f1);

    // L2: f2 = f1 @ w2 + b2 ; fg = groupmax(f2)
    sgemm<1><<<dim3(2, 512), 256>>>(f1, w2, f2, fg, b2, nullptr, nullptr,
                                    65536, 256, 128, 256);
    // fgw = fg @ w3[:256] + b3
    sgemm<0><<<dim3(4, 16), 256>>>(fg, w3, fgw, nullptr, b3, nullptr, nullptr,
                                   2048, 512, 256, 0);
    // f3 = relu(bn2(f2 @ w3[256:] + fgw[group]))
    sgemm<2><<<dim3(4, 512), 256>>>(f2, w3 + 256 * 512, f3, fgw, nullptr, s2, h2,
                                    65536, 512, 256, 0);
    // out = groupmax(f3 @ w4 + b4)
    sgemm<3><<<dim3(3, 512), 256>>>(f3, w4, nullptr, (float*)d_out, b4, nullptr, nullptr,
                                    65536, 384, 512, 384);
}

// round 8
// speedup vs baseline: 1.7751x; 1.7751x over previous
#include <cuda_runtime.h>
#include <cuda_bf16.h>
#include <cstdint>

// ---------------------------------------------------------------------------
// PCDKNNGroupEncoder: FPS -> KNN group -> MLP(6->128 bn relu ->256) ->
//   concat(groupmax, f2) -> 512->512 bn relu -> 384 -> groupmax
// B=32, N=16384, G=64, K=32  => 2048 groups, 65536 MLP rows
// R7: GEMMs on warp-level HMMA (mma.sync m16n8k16 bf16), bf16x3 hi/lo split
//     (tcgen05 unavailable: harness compiles via compute_103 PTX)
// ---------------------------------------------------------------------------

#define NPTS 16384
#define NGRP 64
#define KNN  32

// -------------------- scratch (device globals; no allocation) --------------
__device__ float g_x  [65536 * 6];
__device__ __align__(16) __nv_bfloat16 g_f1h[(size_t)65536 * 128], g_f1l[(size_t)65536 * 128];
__device__ __align__(16) __nv_bfloat16 g_f2h[(size_t)65536 * 256], g_f2l[(size_t)65536 * 256];
__device__ __align__(16) __nv_bfloat16 g_f3h[(size_t)65536 * 512], g_f3l[(size_t)65536 * 512];
__device__ __align__(16) __nv_bfloat16 g_w2th[256 * 128], g_w2tl[256 * 128];   // w2^T
__device__ __align__(16) __nv_bfloat16 g_w3th[512 * 256], g_w3tl[512 * 256];   // w3[256:]^T
__device__ __align__(16) __nv_bfloat16 g_w4th[384 * 512], g_w4tl[384 * 512];   // w4^T
__device__ float g_fg [2048 * 256];
__device__ float g_fgw[2048 * 512];
__device__ int   g_cidx[2048];
__device__ float g_s1[128], g_h1[128], g_s2[512], g_h2[512];

// -------------------- low-level helpers ------------------------------------
__device__ __forceinline__ uint32_t smem_to_u32(const void* p) {
    uint32_t a;
    asm("{ .reg .u64 t; cvta.to.shared.u64 t, %1; cvt.u32.u64 %0, t; }" : "=r"(a) : "l"(p));
    return a;
}
__device__ __forceinline__ void cpasync16(uint32_t dst, const void* src) {
    asm volatile("cp.async.cg.shared.global [%0], [%1], 16;" :: "r"(dst), "l"(src));
}
__device__ __forceinline__ void ldm4(uint32_t* r, uint32_t addr) {
    asm volatile("ldmatrix.sync.aligned.m8n8.x4.shared.b16 {%0,%1,%2,%3}, [%4];"
                 : "=r"(r[0]), "=r"(r[1]), "=r"(r[2]), "=r"(r[3]) : "r"(addr));
}
__device__ __forceinline__ void mma16816(float* d, const uint32_t* a, const uint32_t* b) {
    asm volatile("mma.sync.aligned.m16n8k16.row.col.f32.bf16.bf16.f32 "
                 "{%0,%1,%2,%3}, {%4,%5,%6,%7}, {%8,%9}, {%0,%1,%2,%3};"
                 : "+f"(d[0]), "+f"(d[1]), "+f"(d[2]), "+f"(d[3])
                 : "r"(a[0]), "r"(a[1]), "r"(a[2]), "r"(a[3]), "r"(b[0]), "r"(b[1]));
}

__device__ __forceinline__ unsigned long long wmax64(unsigned long long v) {
#pragma unroll
    for (int o = 16; o; o >>= 1) {
        unsigned long long u = __shfl_xor_sync(0xffffffffu, v, o);
        v = v > u ? v : u;
    }
    return v;
}

__device__ __forceinline__ float dist2(float x, float y, float z,
                                       float cx, float cy, float cz) {
    float dx = __fadd_rn(x, -cx);
    float dy = __fadd_rn(y, -cy);
    float dz = __fadd_rn(z, -cz);
    return __fadd_rn(__fadd_rn(__fmul_rn(dx, dx), __fmul_rn(dy, dy)),
                     __fmul_rn(dz, dz));
}

__device__ __forceinline__ uint32_t bsplit_pack_hi(float a, float b) {
    __nv_bfloat16 ha = __float2bfloat16(a), hb = __float2bfloat16(b);
    return ((uint32_t)__bfloat16_as_ushort(hb) << 16) | __bfloat16_as_ushort(ha);
}
__device__ __forceinline__ uint32_t bsplit_pack_lo(float a, float b) {
    __nv_bfloat16 ha = __float2bfloat16(a), hb = __float2bfloat16(b);
    __nv_bfloat16 la = __float2bfloat16(a - __bfloat162float(ha));
    __nv_bfloat16 lb = __float2bfloat16(b - __bfloat162float(hb));
    return ((uint32_t)__bfloat16_as_ushort(lb) << 16) | __bfloat16_as_ushort(la);
}

// -------------------- bn precompute ----------------------------------------
__global__ void bnprep_kernel(const float* __restrict__ g1, const float* __restrict__ be1,
                              const float* __restrict__ m1, const float* __restrict__ v1,
                              const float* __restrict__ g2, const float* __restrict__ be2,
                              const float* __restrict__ m2, const float* __restrict__ v2,
                              float* __restrict__ s1, float* __restrict__ h1,
                              float* __restrict__ s2, float* __restrict__ h2) {
    int i = threadIdx.x;
    if (i < 128) { float s = g1[i] * rsqrtf(v1[i] + 1e-5f); s1[i] = s; h1[i] = be1[i] - m1[i] * s; }
    if (i < 512) { float s = g2[i] * rsqrtf(v2[i] + 1e-5f); s2[i] = s; h2[i] = be2[i] - m2[i] * s; }
}

// -------------------- weight transpose + bf16 hi/lo split -------------------
__global__ void wprep_kernel(const float* __restrict__ w2, const float* __restrict__ w3,
                             const float* __restrict__ w4,
                             __nv_bfloat16* __restrict__ w2h, __nv_bfloat16* __restrict__ w2l,
                             __nv_bfloat16* __restrict__ w3h, __nv_bfloat16* __restrict__ w3l,
                             __nv_bfloat16* __restrict__ w4h, __nv_bfloat16* __restrict__ w4l) {
    int i = blockIdx.x * 256 + threadIdx.x;
    if (i < 256 * 128) {                 // w2t[n][k] = w2[k][n]
        int n = i >> 7, k = i & 127;
        float v = w2[k * 256 + n];
        __nv_bfloat16 h = __float2bfloat16(v);
        w2h[i] = h; w2l[i] = __float2bfloat16(v - __bfloat162float(h));
    }
    if (i < 512 * 256) {                 // w3t[n][k] = w3[256+k][n]
        int n = i >> 8, k = i & 255;
        float v = w3[(size_t)(256 + k) * 512 + n];
        __nv_bfloat16 h = __float2bfloat16(v);
        w3h[i] = h; w3l[i] = __float2bfloat16(v - __bfloat162float(h));
    }
    if (i < 384 * 512) {                 // w4t[n][k] = w4[k][n]
        int n = i >> 9, k = i & 511;
        float v = w4[(size_t)k * 384 + n];
        __nv_bfloat16 h = __float2bfloat16(v);
        w4h[i] = h; w4l[i] = __float2bfloat16(v - __bfloat162float(h));
    }
}

// -------------------- farthest point sampling (verified) -------------------
__global__ void __launch_bounds__(1024) fps_kernel(const float* __restrict__ pcd,
                                                   int* __restrict__ cidx) {
    int b = blockIdx.x;
    const float* __restrict__ px = pcd + (size_t)b * 6 * NPTS;
    const float* __restrict__ py = px + NPTS;
    const float* __restrict__ pz = px + 2 * NPTS;
    __shared__ unsigned long long red[32];
    __shared__ int scur;
    int tid = threadIdx.x, lane = tid & 31, wid = tid >> 5;

    float dl[16];
#pragma unroll
    for (int j = 0; j < 16; j++) dl[j] = 1e10f;

    int cur = 0;
    for (int it = 0; it < NGRP; it++) {
        if (tid == 0) cidx[b * NGRP + it] = cur;
        float cx = __ldg(px + cur), cy = __ldg(py + cur), cz = __ldg(pz + cur);
        unsigned long long best = 0;
#pragma unroll
        for (int j = 0; j < 16; j++) {
            int p = tid + j * 1024;
            float d2 = dist2(__ldg(px + p), __ldg(py + p), __ldg(pz + p), cx, cy, cz);
            float dn = fminf(dl[j], d2);
            dl[j] = dn;
            unsigned long long key =
                ((unsigned long long)__float_as_uint(dn) << 32) | (unsigned)(16383 - p);
            best = best > key ? best : key;
        }
        best = wmax64(best);
        if (lane == 0) red[wid] = best;
        __syncthreads();
        if (wid == 0) {
            unsigned long long v = wmax64(red[lane]);
            if (lane == 0) scur = 16383 - (int)(v & 0xffffffffu);
        }
        __syncthreads();
        cur = scur;
    }
}

// -------------------- KNN + gather + center subtraction (verified) ---------
__global__ void __launch_bounds__(256) knn_kernel(const float* __restrict__ pcd,
                                                  const int* __restrict__ cidx,
                                                  float* __restrict__ xf) {
    int gw = (int)((blockIdx.x * 256 + threadIdx.x) >> 5);
    int lane = threadIdx.x & 31;
    int b = gw >> 6;
    const float* __restrict__ px = pcd + (size_t)b * 6 * NPTS;
    const float* __restrict__ py = px + NPTS;
    const float* __restrict__ pz = py + NPTS;
    const float* __restrict__ p3 = pz + NPTS;
    const float* __restrict__ p4 = p3 + NPTS;
    const float* __restrict__ p5 = p4 + NPTS;

    int ci = cidx[gw];
    float cx = __ldg(px + ci), cy = __ldg(py + ci), cz = __ldg(pz + ci);

    float d0 = dist2(__ldg(px + lane), __ldg(py + lane), __ldg(pz + lane), cx, cy, cz);
    unsigned long long held = ((unsigned long long)__float_as_uint(d0) << 32) | (unsigned)lane;
    unsigned long long thr = wmax64(held);

    for (int base = 32; base < NPTS; base += 32) {
        int n = base + lane;
        float d2 = dist2(__ldg(px + n), __ldg(py + n), __ldg(pz + n), cx, cy, cz);
        unsigned long long key = ((unsigned long long)__float_as_uint(d2) << 32) | (unsigned)n;
        unsigned qm = __ballot_sync(0xffffffffu, key < thr);
        while (qm) {
            int src = __ffs(qm) - 1;
            qm &= qm - 1;
            unsigned long long cand = __shfl_sync(0xffffffffu, key, src);
            if (cand < thr) {
                unsigned rm = __ballot_sync(0xffffffffu, held == thr);
                if (lane == __ffs(rm) - 1) held = cand;
                thr = wmax64(held);
            }
        }
    }
    int n = (int)(held & 0xffffffffu);
    size_t row = (size_t)gw * KNN + lane;
    float* o = xf + row * 6;
    o[0] = __fadd_rn(__ldg(px + n), -cx);
    o[1] = __fadd_rn(__ldg(py + n), -cy);
    o[2] = __fadd_rn(__ldg(pz + n), -cz);
    o[3] = __ldg(p3 + n);
    o[4] = __ldg(p4 + n);
    o[5] = __ldg(p5 + n);
}

// -------------------- layer1: 6 -> 128 + bn1 + relu -> bf16 hi/lo ----------
__global__ void __launch_bounds__(256) layer1_kernel(const float* __restrict__ xf,
                                                     const float* __restrict__ w1,
                                                     const float* __restrict__ b1,
                                                     const float* __restrict__ s1,
                                                     const float* __restrict__ h1,
                                                     __nv_bfloat16* __restrict__ f1h,
                                                     __nv_bfloat16* __restrict__ f1l) {
    __shared__ float ws[768];
    __shared__ float bs[128], sc[128], sh[128];
    __shared__ float xs[384];
    int tid = threadIdx.x;
    size_t rowBase = (size_t)blockIdx.x * 64;
    for (int i = tid; i < 768; i += 256) ws[i] = w1[i];
    if (tid < 128) { bs[tid] = b1[tid]; sc[tid] = s1[tid]; sh[tid] = h1[tid]; }
    for (int i = tid; i < 384; i += 256) xs[i] = xf[rowBase * 6 + i];
    __syncthreads();
#pragma unroll 4
    for (int i = 0; i < 32; i++) {
        int o = i * 256 + tid;
        int col = o & 127, r = o >> 7;
        float acc = bs[col];
#pragma unroll
        for (int j = 0; j < 6; j++) acc = fmaf(xs[r * 6 + j], ws[j * 128 + col], acc);
        float v = fmaxf(fmaf(acc, sc[col], sh[col]), 0.f);
        __nv_bfloat16 h = __float2bfloat16(v);
        size_t idx = (rowBase + r) * 128 + col;
        f1h[idx] = h;
        f1l[idx] = __float2bfloat16(v - __bfloat162float(h));
    }
}

// ---------------------------------------------------------------------------
// HMMA bf16x3 GEMM. CTA tile 128x128, 8 warps (warp tile 32x64), K-chunk 32,
// cp.async double-buffered. Accum f32 in registers (m16n8k16 fragments).
// D = Ah*Bh + Al*Bh + Ah*Bl   (A rows [M][KTOT], B rows = W^T [N][KTOT])
// EPI 1: v = D + bias -> store C hi/lo; aux[g][c] = groupmax(v)    (L2)
// EPI 2: v = relu((D + fgw[g][c]) * sc[c] + sh[c]) -> store C hi/lo (L3)
// EPI 3: v = D + bias -> aux[g][c] = groupmax(v); no C store        (L4)
// ---------------------------------------------------------------------------
#define ROWB 80                       // smem row stride bytes (64B data + 16 pad)
#define TERM 10240                    // 128 rows * 80B, one term tile
#define STAGE 40960                   // Ah | Al | Bh | Bl

template <int KTOT, int NOUT, int EPI>
__global__ void __launch_bounds__(256, 1)
tgemm(const __nv_bfloat16* __restrict__ Ah, const __nv_bfloat16* __restrict__ Al,
      const __nv_bfloat16* __restrict__ Bh, const __nv_bfloat16* __restrict__ Bl,
      const float* __restrict__ bias, const float* __restrict__ fgw,
      const float* __restrict__ scv, const float* __restrict__ shv,
      __nv_bfloat16* __restrict__ Ch, __nv_bfloat16* __restrict__ Cl,
      float* __restrict__ aux) {
    constexpr int NCH = KTOT / 32;
    extern __shared__ char smemc[];
    uint32_t sb = smem_to_u32(smemc);

    int tid = threadIdx.x, lane = tid & 31, wid = tid >> 5;
    int wm = wid & 3, wn = wid >> 2;
    int mBase = (int)blockIdx.y << 7;
    int nBase = (int)blockIdx.x << 7;

    float acc[2][8][4];
#pragma unroll
    for (int mi = 0; mi < 2; mi++)
#pragma unroll
        for (int nj = 0; nj < 8; nj++)
#pragma unroll
            for (int q = 0; q < 4; q++) acc[mi][nj][q] = 0.f;

    // ---- async loader for one k-chunk ----
    auto load_chunk = [&](int t) {
        int k0 = t * 32;
        uint32_t dstS = sb + (uint32_t)(t & 1) * STAGE;
#pragma unroll
        for (int rep = 0; rep < 4; rep++) {          // A: 1024 16B segs
            int i = rep * 256 + tid;
            int term = i >> 9, row = (i >> 2) & 127, seg = i & 3;
            const __nv_bfloat16* src =
                (term ? Al : Ah) + (size_t)(mBase + row) * KTOT + (k0 + seg * 8);
            cpasync16(dstS + term * TERM + row * ROWB + seg * 16, src);
        }
#pragma unroll
        for (int rep = 0; rep < 4; rep++) {          // B: 1024 16B segs
            int i = rep * 256 + tid;
            int term = i >> 9, row = (i >> 2) & 127, seg = i & 3;
            const __nv_bfloat16* src =
                (term ? Bl : Bh) + (size_t)(nBase + row) * KTOT + (k0 + seg * 8);
            cpasync16(dstS + 2 * TERM + term * TERM + row * ROWB + seg * 16, src);
        }
    };

    // per-lane ldmatrix base offsets
    uint32_t aOff = (uint32_t)((wm * 32 + (lane & 7) + ((lane >> 3) & 1) * 8) * ROWB +
                               ((lane >> 4) & 1) * 16);
    uint32_t bOff = (uint32_t)(2 * TERM +
                               (wn * 64 + (lane & 7) + ((lane >> 4) & 1) * 8) * ROWB +
                               ((lane >> 3) & 1) * 16);

    load_chunk(0);
    asm volatile("cp.async.commit_group;");

    for (int t = 0; t < NCH; t++) {
        if (t + 1 < NCH) {
            load_chunk(t + 1);
            asm volatile("cp.async.commit_group;");
            asm volatile("cp.async.wait_group 1;");
        } else {
            asm volatile("cp.async.wait_group 0;");
        }
        __syncthreads();

        uint32_t s0 = sb + (uint32_t)(t & 1) * STAGE;
#pragma unroll
        for (int ks = 0; ks < 2; ks++) {
            uint32_t ka = s0 + aOff + ks * 32;
            uint32_t kb = s0 + bOff + ks * 32;
            uint32_t ah[8], al[8], bh[16], bl[16];
            ldm4(ah, ka);
            ldm4(ah + 4, ka + 16 * ROWB);
            ldm4(al, ka + TERM);
            ldm4(al + 4, ka + TERM + 16 * ROWB);
#pragma unroll
            for (int p = 0; p < 4; p++) ldm4(bh + p * 4, kb + p * 16 * ROWB);
#pragma unroll
            for (int p = 0; p < 4; p++) ldm4(bl + p * 4, kb + TERM + p * 16 * ROWB);
#pragma unroll
            for (int mi = 0; mi < 2; mi++)
#pragma unroll
                for (int nj = 0; nj < 8; nj++) {
                    const uint32_t* fh = bh + (nj >> 1) * 4 + (nj & 1) * 2;
                    const uint32_t* fl = bl + (nj >> 1) * 4 + (nj & 1) * 2;
                    mma16816(acc[mi][nj], ah + mi * 4, fh);
                    mma16816(acc[mi][nj], al + mi * 4, fh);
                    mma16816(acc[mi][nj], ah + mi * 4, fl);
                }
        }
        __syncthreads();
    }

    // ---- epilogue ----
    int lr = lane >> 2, lc = (lane & 3) * 2;
    int g = (mBase >> 5) + wm;                      // 32-row group == warp M tile
    int mrow0 = mBase + wm * 32 + lr;
    int cBase = nBase + wn * 64 + lc;

#pragma unroll
    for (int nj = 0; nj < 8; nj++) {
        int c = cBase + nj * 8;
        float v[2][2][2];
        if (EPI == 2) {
            float2 fw = *(const float2*)(fgw + (size_t)g * 512 + c);
            float2 s2 = *(const float2*)(scv + c);
            float2 h2 = *(const float2*)(shv + c);
#pragma unroll
            for (int mi = 0; mi < 2; mi++)
#pragma unroll
                for (int h = 0; h < 2; h++) {
                    v[mi][h][0] = fmaxf(fmaf(acc[mi][nj][h * 2] + fw.x, s2.x, h2.x), 0.f);
                    v[mi][h][1] = fmaxf(fmaf(acc[mi][nj][h * 2 + 1] + fw.y, s2.y, h2.y), 0.f);
                }
        } else {
            float2 bb = *(const float2*)(bias + c);
#pragma unroll
            for (int mi = 0; mi < 2; mi++)
#pragma unroll
                for (int h = 0; h < 2; h++) {
                    v[mi][h][0] = acc[mi][nj][h * 2] + bb.x;
                    v[mi][h][1] = acc[mi][nj][h * 2 + 1] + bb.y;
                }
        }
        if (EPI != 3) {
#pragma unroll
            for (int mi = 0; mi < 2; mi++)
#pragma unroll
                for (int h = 0; h < 2; h++) {
                    int row = mrow0 + mi * 16 + h * 8;
                    *(uint32_t*)(Ch + (size_t)row * NOUT + c) =
                        bsplit_pack_hi(v[mi][h][0], v[mi][h][1]);
                    *(uint32_t*)(Cl + (size_t)row * NOUT + c) =
                        bsplit_pack_lo(v[mi][h][0], v[mi][h][1]);
                }
        }
        if (EPI != 2) {
            float m0 = fmaxf(fmaxf(v[0][0][0], v[0][1][0]), fmaxf(v[1][0][0], v[1][1][0]));
            float m1 = fmaxf(fmaxf(v[0][0][1], v[0][1][1]), fmaxf(v[1][0][1], v[1][1][1]));
#pragma unroll
            for (int o = 4; o < 32; o <<= 1) {
                m0 = fmaxf(m0, __shfl_xor_sync(0xffffffffu, m0, o));
                m1 = fmaxf(m1, __shfl_xor_sync(0xffffffffu, m1, o));
            }
            if (lane < 4) {
                aux[(size_t)g * NOUT + c] = m0;
                aux[(size_t)g * NOUT + c + 1] = m1;
            }
        }
    }
}

// -------------------- small fp32 GEMM for fgw = fg @ w3[:256] + b3 ----------
template <int EPI>
__global__ void __launch_bounds__(256) sgemm(const float* __restrict__ A,
                                             const float* __restrict__ Bm,
                                             float* __restrict__ C,
                                             float* __restrict__ aux,
                                             const float* __restrict__ bias,
                                             const float* __restrict__ scale,
                                             const float* __restrict__ shift,
                                             int M, int N, int K, int auxN) {
    __shared__ float As[2][16][132];
    __shared__ float Bs[2][16][128];

    int tid = threadIdx.x;
    int tx = tid & 15, ty = tid >> 4;
    int mBase = blockIdx.y << 7, nBase = blockIdx.x << 7;

    int aK = tid & 15, aM = tid >> 4;
    int bN = (tid & 31) << 2, bK = tid >> 5;

    const float* Ap = A + (size_t)(mBase + aM) * K + aK;
    const float* Bp = Bm + (size_t)bK * N + nBase + bN;

    float acc[8][8];
#pragma unroll
    for (int i = 0; i < 8; i++)
#pragma unroll
        for (int j = 0; j < 8; j++) acc[i][j] = 0.f;

    float ar[8];
    float4 br[2];
    int nt = K >> 4;

#pragma unroll
    for (int e = 0; e < 8; e++) ar[e] = Ap[(size_t)(e * 16) * K];
#pragma unroll
    for (int e = 0; e < 2; e++) br[e] = *(const float4*)(Bp + (size_t)(e * 8) * N);
#pragma unroll
    for (int e = 0; e < 8; e++) As[0][aK][aM + e * 16] = ar[e];
#pragma unroll
    for (int e = 0; e < 2; e++) *(float4*)&Bs[0][bK + e * 8][bN] = br[e];
    __syncthreads();

    for (int t = 0; t < nt; t++) {
        int buf = t & 1;
        if (t + 1 < nt) {
            int kOff = (t + 1) << 4;
#pragma unroll
            for (int e = 0; e < 8; e++) ar[e] = Ap[(size_t)(e * 16) * K + kOff];
#pragma unroll
            for (int e = 0; e < 2; e++)
                br[e] = *(const float4*)(Bp + (size_t)(kOff + e * 8) * N);
        }
#pragma unroll
        for (int kk = 0; kk < 16; kk++) {
            float a[8], bb[8];
            *(float4*)&a[0]  = *(const float4*)&As[buf][kk][ty * 8];
            *(float4*)&a[4]  = *(const float4*)&As[buf][kk][ty * 8 + 4];
            *(float4*)&bb[0] = *(const float4*)&Bs[buf][kk][tx * 8];
            *(float4*)&bb[4] = *(const float4*)&Bs[buf][kk][tx * 8 + 4];
#pragma unroll
            for (int i = 0; i < 8; i++)
#pragma unroll
                for (int j = 0; j < 8; j++) acc[i][j] = fmaf(a[i], bb[j], acc[i][j]);
        }
        if (t + 1 < nt) {
            int nb = buf ^ 1;
#pragma unroll
            for (int e = 0; e < 8; e++) As[nb][aK][aM + e * 16] = ar[e];
#pragma unroll
            for (int e = 0; e < 2; e++) *(float4*)&Bs[nb][bK + e * 8][bN] = br[e];
            __syncthreads();
        }
    }

    int colBase = nBase + tx * 8;
    float bb8[8];
#pragma unroll
    for (int j = 0; j < 8; j++) bb8[j] = __ldg(bias + colBase + j);
#pragma unroll
    for (int i = 0; i < 8; i++) {
#pragma unroll
        for (int j = 0; j < 8; j++) acc[i][j] += bb8[j];
        float* cp = C + (size_t)(mBase + ty * 8 + i) * N + colBase;
        *(float4*)cp = *(float4*)&acc[i][0];
        *(float4*)(cp + 4) = *(float4*)&acc[i][4];
    }
}

// ---------------------------------------------------------------------------
extern "C" void kernel_launch(void* const* d_in, const int* in_sizes, int n_in,
                              void* d_out, int out_size) {
    (void)in_sizes; (void)n_in; (void)out_size;
    const float* pcd = (const float*)d_in[0];
    const float* w1  = (const float*)d_in[2];
    const float* b1  = (const float*)d_in[3];
    const float* g1  = (const float*)d_in[4];
    const float* be1 = (const float*)d_in[5];
    const float* m1  = (const float*)d_in[6];
    const float* v1  = (const float*)d_in[7];
    const float* w2  = (const float*)d_in[8];
    const float* b2  = (const float*)d_in[9];
    const float* w3  = (const float*)d_in[10];
    const float* b3  = (const float*)d_in[11];
    const float* g2  = (const float*)d_in[12];
    const float* be2 = (const float*)d_in[13];
    const float* m2  = (const float*)d_in[14];
    const float* v2  = (const float*)d_in[15];
    const float* w4  = (const float*)d_in[16];
    const float* b4  = (const float*)d_in[17];

    float *xf, *fg, *fgw, *s1, *h1, *s2, *h2;
    __nv_bfloat16 *f1h, *f1l, *f2h, *f2l, *f3h, *f3l;
    __nv_bfloat16 *w2th, *w2tl, *w3th, *w3tl, *w4th, *w4tl;
    int* ci;
    cudaGetSymbolAddress((void**)&xf,   g_x);
    cudaGetSymbolAddress((void**)&f1h,  g_f1h);  cudaGetSymbolAddress((void**)&f1l, g_f1l);
    cudaGetSymbolAddress((void**)&f2h,  g_f2h);  cudaGetSymbolAddress((void**)&f2l, g_f2l);
    cudaGetSymbolAddress((void**)&f3h,  g_f3h);  cudaGetSymbolAddress((void**)&f3l, g_f3l);
    cudaGetSymbolAddress((void**)&w2th, g_w2th); cudaGetSymbolAddress((void**)&w2tl, g_w2tl);
    cudaGetSymbolAddress((void**)&w3th, g_w3th); cudaGetSymbolAddress((void**)&w3tl, g_w3tl);
    cudaGetSymbolAddress((void**)&w4th, g_w4th); cudaGetSymbolAddress((void**)&w4tl, g_w4tl);
    cudaGetSymbolAddress((void**)&fg,   g_fg);
    cudaGetSymbolAddress((void**)&fgw,  g_fgw);
    cudaGetSymbolAddress((void**)&ci,   g_cidx);
    cudaGetSymbolAddress((void**)&s1,   g_s1);
    cudaGetSymbolAddress((void**)&h1,   g_h1);
    cudaGetSymbolAddress((void**)&s2,   g_s2);
    cudaGetSymbolAddress((void**)&h2,   g_h2);

    constexpr int SMEM_T = 2 * STAGE;   // 81920
    cudaFuncSetAttribute(tgemm<128, 256, 1>, cudaFuncAttributeMaxDynamicSharedMemorySize, SMEM_T);
    cudaFuncSetAttribute(tgemm<256, 512, 2>, cudaFuncAttributeMaxDynamicSharedMemorySize, SMEM_T);
    cudaFuncSetAttribute(tgemm<512, 384, 3>, cudaFuncAttributeMaxDynamicSharedMemorySize, SMEM_T);

    bnprep_kernel<<<1, 512>>>(g1, be1, m1, v1, g2, be2, m2, v2, s1, h1, s2, h2);
    wprep_kernel<<<768, 256>>>(w2, w3, w4, w2th, w2tl, w3th, w3tl, w4th, w4tl);
    fps_kernel<<<32, 1024>>>(pcd, ci);
    knn_kernel<<<256, 256>>>(pcd, ci, xf);
    layer1_kernel<<<1024, 256>>>(xf, w1, b1, s1, h1, f1h, f1l);

    // L2: f2 = f1 @ w2 + b2 ; fg = groupmax(f2)
    tgemm<128, 256, 1><<<dim3(2, 512), 256, SMEM_T>>>(
        f1h, f1l, w2th, w2tl, b2, nullptr, nullptr, nullptr, f2h, f2l, fg);
    // fgw = fg @ w3[:256] + b3   (fp32, tiny)
    sgemm<0><<<dim3(4, 16), 256>>>(fg, w3, fgw, nullptr, b3, nullptr, nullptr,
                                   2048, 512, 256, 0);
    // f3 = relu(bn2(f2 @ w3[256:] + fgw[group]))
    tgemm<256, 512, 2><<<dim3(4, 512), 256, SMEM_T>>>(
        f2h, f2l, w3th, w3tl, nullptr, fgw, s2, h2, f3h, f3l, nullptr);
    // out = groupmax(f3 @ w4 + b4)
    tgemm<512, 384, 3><<<dim3(3, 512), 256, SMEM_T>>>(
        f3h, f3l, w4th, w4tl, b4, nullptr, nullptr, nullptr, nullptr, nullptr,
        (float*)d_out);
}

// round 13
// speedup vs baseline: 1.7863x; 1.0063x over previous
#include <cuda_runtime.h>
#include <cuda_bf16.h>
#include <cstdint>

// ---------------------------------------------------------------------------
// PCDKNNGroupEncoder: FPS -> KNN group -> MLP(6->128 bn relu ->256) ->
//   concat(groupmax, f2) -> 512->512 bn relu -> 384 -> groupmax
// B=32, N=16384, G=64, K=32  => 2048 groups, 65536 MLP rows
// R9: KNN split 8 warps/group + bitonic merge; FPS single-barrier reduction.
//     GEMMs: warp-level HMMA bf16x3 (unchanged from R8).
// ---------------------------------------------------------------------------

#define NPTS 16384
#define NGRP 64
#define KNN  32

// -------------------- scratch (device globals; no allocation) --------------
__device__ float g_x  [65536 * 6];
__device__ __align__(16) __nv_bfloat16 g_f1h[(size_t)65536 * 128], g_f1l[(size_t)65536 * 128];
__device__ __align__(16) __nv_bfloat16 g_f2h[(size_t)65536 * 256], g_f2l[(size_t)65536 * 256];
__device__ __align__(16) __nv_bfloat16 g_f3h[(size_t)65536 * 512], g_f3l[(size_t)65536 * 512];
__device__ __align__(16) __nv_bfloat16 g_w2th[256 * 128], g_w2tl[256 * 128];   // w2^T
__device__ __align__(16) __nv_bfloat16 g_w3th[512 * 256], g_w3tl[512 * 256];   // w3[256:]^T
__device__ __align__(16) __nv_bfloat16 g_w4th[384 * 512], g_w4tl[384 * 512];   // w4^T
__device__ float g_fg [2048 * 256];
__device__ float g_fgw[2048 * 512];
__device__ int   g_cidx[2048];
__device__ float g_s1[128], g_h1[128], g_s2[512], g_h2[512];

// -------------------- low-level helpers ------------------------------------
__device__ __forceinline__ uint32_t smem_to_u32(const void* p) {
    uint32_t a;
    asm("{ .reg .u64 t; cvta.to.shared.u64 t, %1; cvt.u32.u64 %0, t; }" : "=r"(a) : "l"(p));
    return a;
}
__device__ __forceinline__ void cpasync16(uint32_t dst, const void* src) {
    asm volatile("cp.async.cg.shared.global [%0], [%1], 16;" :: "r"(dst), "l"(src));
}
__device__ __forceinline__ void ldm4(uint32_t* r, uint32_t addr) {
    asm volatile("ldmatrix.sync.aligned.m8n8.x4.shared.b16 {%0,%1,%2,%3}, [%4];"
                 : "=r"(r[0]), "=r"(r[1]), "=r"(r[2]), "=r"(r[3]) : "r"(addr));
}
__device__ __forceinline__ void mma16816(float* d, const uint32_t* a, const uint32_t* b) {
    asm volatile("mma.sync.aligned.m16n8k16.row.col.f32.bf16.bf16.f32 "
                 "{%0,%1,%2,%3}, {%4,%5,%6,%7}, {%8,%9}, {%0,%1,%2,%3};"
                 : "+f"(d[0]), "+f"(d[1]), "+f"(d[2]), "+f"(d[3])
                 : "r"(a[0]), "r"(a[1]), "r"(a[2]), "r"(a[3]), "r"(b[0]), "r"(b[1]));
}

__device__ __forceinline__ unsigned long long wmax64(unsigned long long v) {
#pragma unroll
    for (int o = 16; o; o >>= 1) {
        unsigned long long u = __shfl_xor_sync(0xffffffffu, v, o);
        v = v > u ? v : u;
    }
    return v;
}

__device__ __forceinline__ float dist2(float x, float y, float z,
                                       float cx, float cy, float cz) {
    float dx = __fadd_rn(x, -cx);
    float dy = __fadd_rn(y, -cy);
    float dz = __fadd_rn(z, -cz);
    return __fadd_rn(__fadd_rn(__fmul_rn(dx, dx), __fmul_rn(dy, dy)),
                     __fmul_rn(dz, dz));
}

__device__ __forceinline__ uint32_t bsplit_pack_hi(float a, float b) {
    __nv_bfloat16 ha = __float2bfloat16(a), hb = __float2bfloat16(b);
    return ((uint32_t)__bfloat16_as_ushort(hb) << 16) | __bfloat16_as_ushort(ha);
}
__device__ __forceinline__ uint32_t bsplit_pack_lo(float a, float b) {
    __nv_bfloat16 ha = __float2bfloat16(a), hb = __float2bfloat16(b);
    __nv_bfloat16 la = __float2bfloat16(a - __bfloat162float(ha));
    __nv_bfloat16 lb = __float2bfloat16(b - __bfloat162float(hb));
    return ((uint32_t)__bfloat16_as_ushort(lb) << 16) | __bfloat16_as_ushort(la);
}

// -------------------- bn precompute ----------------------------------------
__global__ void bnprep_kernel(const float* __restrict__ g1, const float* __restrict__ be1,
                              const float* __restrict__ m1, const float* __restrict__ v1,
                              const float* __restrict__ g2, const float* __restrict__ be2,
                              const float* __restrict__ m2, const float* __restrict__ v2,
                              float* __restrict__ s1, float* __restrict__ h1,
                              float* __restrict__ s2, float* __restrict__ h2) {
    int i = threadIdx.x;
    if (i < 128) { float s = g1[i] * rsqrtf(v1[i] + 1e-5f); s1[i] = s; h1[i] = be1[i] - m1[i] * s; }
    if (i < 512) { float s = g2[i] * rsqrtf(v2[i] + 1e-5f); s2[i] = s; h2[i] = be2[i] - m2[i] * s; }
}

// -------------------- weight transpose + bf16 hi/lo split -------------------
__global__ void wprep_kernel(const float* __restrict__ w2, const float* __restrict__ w3,
                             const float* __restrict__ w4,
                             __nv_bfloat16* __restrict__ w2h, __nv_bfloat16* __restrict__ w2l,
                             __nv_bfloat16* __restrict__ w3h, __nv_bfloat16* __restrict__ w3l,
                             __nv_bfloat16* __restrict__ w4h, __nv_bfloat16* __restrict__ w4l) {
    int i = blockIdx.x * 256 + threadIdx.x;
    if (i < 256 * 128) {                 // w2t[n][k] = w2[k][n]
        int n = i >> 7, k = i & 127;
        float v = w2[k * 256 + n];
        __nv_bfloat16 h = __float2bfloat16(v);
        w2h[i] = h; w2l[i] = __float2bfloat16(v - __bfloat162float(h));
    }
    if (i < 512 * 256) {                 // w3t[n][k] = w3[256+k][n]
        int n = i >> 8, k = i & 255;
        float v = w3[(size_t)(256 + k) * 512 + n];
        __nv_bfloat16 h = __float2bfloat16(v);
        w3h[i] = h; w3l[i] = __float2bfloat16(v - __bfloat162float(h));
    }
    if (i < 384 * 512) {                 // w4t[n][k] = w4[k][n]
        int n = i >> 9, k = i & 511;
        float v = w4[(size_t)k * 384 + n];
        __nv_bfloat16 h = __float2bfloat16(v);
        w4h[i] = h; w4l[i] = __float2bfloat16(v - __bfloat162float(h));
    }
}

// -------------------- farthest point sampling (1 barrier / iter) -----------
__global__ void __launch_bounds__(1024) fps_kernel(const float* __restrict__ pcd,
                                                   int* __restrict__ cidx) {
    int b = blockIdx.x;
    const float* __restrict__ px = pcd + (size_t)b * 6 * NPTS;
    const float* __restrict__ py = px + NPTS;
    const float* __restrict__ pz = px + 2 * NPTS;
    __shared__ unsigned long long red[2][32];
    int tid = threadIdx.x, lane = tid & 31, wid = tid >> 5;

    float dl[16];
#pragma unroll
    for (int j = 0; j < 16; j++) dl[j] = 1e10f;

    int cur = 0;
    for (int it = 0; it < NGRP; it++) {
        if (tid == 0) cidx[b * NGRP + it] = cur;
        float cx = __ldg(px + cur), cy = __ldg(py + cur), cz = __ldg(pz + cur);
        unsigned long long best = 0;
#pragma unroll
        for (int j = 0; j < 16; j++) {
            int p = tid + j * 1024;
            float d2 = dist2(__ldg(px + p), __ldg(py + p), __ldg(pz + p), cx, cy, cz);
            float dn = fminf(dl[j], d2);
            dl[j] = dn;
            unsigned long long key =
                ((unsigned long long)__float_as_uint(dn) << 32) | (unsigned)(16383 - p);
            best = best > key ? best : key;
        }
        best = wmax64(best);
        int buf = it & 1;
        if (lane == 0) red[buf][wid] = best;
        __syncthreads();
        // every warp redundantly reduces the 32 partials; no second barrier
        unsigned long long v = wmax64(red[buf][lane]);
        cur = 16383 - (int)(v & 0xffffffffu);
    }
}

// -------------------- KNN: 8 warps/group + bitonic merge --------------------
// Each warp threshold-inserts top-32 of its 2048-point segment; the 8 partial
// sets (256 keys) are bitonic-sorted in smem; 32 smallest = exact top_k set.
// Neighbor ORDER is irrelevant: downstream only uses max over K.
__global__ void __launch_bounds__(256) knn_kernel(const float* __restrict__ pcd,
                                                  const int* __restrict__ cidx,
                                                  float* __restrict__ xf) {
    int grp = blockIdx.x;                      // 0..2047
    int lane = threadIdx.x & 31, wid = threadIdx.x >> 5;
    int b = grp >> 6;
    const float* __restrict__ px = pcd + (size_t)b * 6 * NPTS;
    const float* __restrict__ py = px + NPTS;
    const float* __restrict__ pz = py + NPTS;
    const float* __restrict__ p3 = pz + NPTS;
    const float* __restrict__ p4 = p3 + NPTS;
    const float* __restrict__ p5 = p4 + NPTS;

    __shared__ unsigned long long keys[256];

    int ci = cidx[grp];
    float cx = __ldg(px + ci), cy = __ldg(py + ci), cz = __ldg(pz + ci);

    int s0 = wid << 11;                        // 2048-point segment per warp
    int p0 = s0 + lane;
    float d0 = dist2(__ldg(px + p0), __ldg(py + p0), __ldg(pz + p0), cx, cy, cz);
    unsigned long long held = ((unsigned long long)__float_as_uint(d0) << 32) | (unsigned)p0;
    unsigned long long thr = wmax64(held);

    for (int base = s0 + 32; base < s0 + 2048; base += 32) {
        int n = base + lane;
        float d2 = dist2(__ldg(px + n), __ldg(py + n), __ldg(pz + n), cx, cy, cz);
        unsigned long long key = ((unsigned long long)__float_as_uint(d2) << 32) | (unsigned)n;
        unsigned qm = __ballot_sync(0xffffffffu, key < thr);
        while (qm) {
            int src = __ffs(qm) - 1;
            qm &= qm - 1;
            unsigned long long cand = __shfl_sync(0xffffffffu, key, src);
            if (cand < thr) {                   // uniform branch
                unsigned rm = __ballot_sync(0xffffffffu, held == thr);
                if (lane == __ffs(rm) - 1) held = cand;
                thr = wmax64(held);
            }
        }
    }
    keys[(wid << 5) + lane] = held;
    __syncthreads();

    // bitonic sort of 256 u64 keys, ascending
    int i = threadIdx.x;
#pragma unroll
    for (int k = 2; k <= 256; k <<= 1) {
#pragma unroll
        for (int j = k >> 1; j > 0; j >>= 1) {
            int ixj = i ^ j;
            if (ixj > i) {
                unsigned long long a = keys[i], c = keys[ixj];
                bool up = (i & k) == 0;
                if ((a > c) == up) { keys[i] = c; keys[ixj] = a; }
            }
            __syncthreads();
        }
    }

    if (i < 32) {                              // 32 smallest keys = kNN set
        int n = (int)(keys[i] & 0xffffffffu);
        size_t row = (size_t)grp * KNN + i;
        float* o = xf + row * 6;
        o[0] = __fadd_rn(__ldg(px + n), -cx);
        o[1] = __fadd_rn(__ldg(py + n), -cy);
        o[2] = __fadd_rn(__ldg(pz + n), -cz);
        o[3] = __ldg(p3 + n);
        o[4] = __ldg(p4 + n);
        o[5] = __ldg(p5 + n);
    }
}

// -------------------- layer1: 6 -> 128 + bn1 + relu -> bf16 hi/lo ----------
__global__ void __launch_bounds__(256) layer1_kernel(const float* __restrict__ xf,
                                                     const float* __restrict__ w1,
                                                     const float* __restrict__ b1,
                                                     const float* __restrict__ s1,
                                                     const float* __restrict__ h1,
                                                     __nv_bfloat16* __restrict__ f1h,
                                                     __nv_bfloat16* __restrict__ f1l) {
    __shared__ float ws[768];
    __shared__ float bs[128], sc[128], sh[128];
    __shared__ float xs[384];
    int tid = threadIdx.x;
    size_t rowBase = (size_t)blockIdx.x * 64;
    for (int i = tid; i < 768; i += 256) ws[i] = w1[i];
    if (tid < 128) { bs[tid] = b1[tid]; sc[tid] = s1[tid]; sh[tid] = h1[tid]; }
    for (int i = tid; i < 384; i += 256) xs[i] = xf[rowBase * 6 + i];
    __syncthreads();
#pragma unroll 4
    for (int i = 0; i < 32; i++) {
        int o = i * 256 + tid;
        int col = o & 127, r = o >> 7;
        float acc = bs[col];
#pragma unroll
        for (int j = 0; j < 6; j++) acc = fmaf(xs[r * 6 + j], ws[j * 128 + col], acc);
        float v = fmaxf(fmaf(acc, sc[col], sh[col]), 0.f);
        __nv_bfloat16 h = __float2bfloat16(v);
        size_t idx = (rowBase + r) * 128 + col;
        f1h[idx] = h;
        f1l[idx] = __float2bfloat16(v - __bfloat162float(h));
    }
}

// ---------------------------------------------------------------------------
// HMMA bf16x3 GEMM. CTA tile 128x128, 8 warps (warp tile 32x64), K-chunk 32,
// cp.async double-buffered. Accum f32 in registers (m16n8k16 fragments).
// D = Ah*Bh + Al*Bh + Ah*Bl   (A rows [M][KTOT], B rows = W^T [N][KTOT])
// EPI 1: v = D + bias -> store C hi/lo; aux[g][c] = groupmax(v)    (L2)
// EPI 2: v = relu((D + fgw[g][c]) * sc[c] + sh[c]) -> store C hi/lo (L3)
// EPI 3: v = D + bias -> aux[g][c] = groupmax(v); no C store        (L4)
// ---------------------------------------------------------------------------
#define ROWB 80                       // smem row stride bytes (64B data + 16 pad)
#define TERM 10240                    // 128 rows * 80B, one term tile
#define STAGE 40960                   // Ah | Al | Bh | Bl

template <int KTOT, int NOUT, int EPI>
__global__ void __launch_bounds__(256, 1)
tgemm(const __nv_bfloat16* __restrict__ Ah, const __nv_bfloat16* __restrict__ Al,
      const __nv_bfloat16* __restrict__ Bh, const __nv_bfloat16* __restrict__ Bl,
      const float* __restrict__ bias, const float* __restrict__ fgw,
      const float* __restrict__ scv, const float* __restrict__ shv,
      __nv_bfloat16* __restrict__ Ch, __nv_bfloat16* __restrict__ Cl,
      float* __restrict__ aux) {
    constexpr int NCH = KTOT / 32;
    extern __shared__ char smemc[];
    uint32_t sb = smem_to_u32(smemc);

    int tid = threadIdx.x, lane = tid & 31, wid = tid >> 5;
    int wm = wid & 3, wn = wid >> 2;
    int mBase = (int)blockIdx.y << 7;
    int nBase = (int)blockIdx.x << 7;

    float acc[2][8][4];
#pragma unroll
    for (int mi = 0; mi < 2; mi++)
#pragma unroll
        for (int nj = 0; nj < 8; nj++)
#pragma unroll
            for (int q = 0; q < 4; q++) acc[mi][nj][q] = 0.f;

    auto load_chunk = [&](int t) {
        int k0 = t * 32;
        uint32_t dstS = sb + (uint32_t)(t & 1) * STAGE;
#pragma unroll
        for (int rep = 0; rep < 4; rep++) {          // A: 1024 16B segs
            int i = rep * 256 + tid;
            int term = i >> 9, row = (i >> 2) & 127, seg = i & 3;
            const __nv_bfloat16* src =
                (term ? Al : Ah) + (size_t)(mBase + row) * KTOT + (k0 + seg * 8);
            cpasync16(dstS + term * TERM + row * ROWB + seg * 16, src);
        }
#pragma unroll
        for (int rep = 0; rep < 4; rep++) {          // B: 1024 16B segs
            int i = rep * 256 + tid;
            int term = i >> 9, row = (i >> 2) & 127, seg = i & 3;
            const __nv_bfloat16* src =
                (term ? Bl : Bh) + (size_t)(nBase + row) * KTOT + (k0 + seg * 8);
            cpasync16(dstS + 2 * TERM + term * TERM + row * ROWB + seg * 16, src);
        }
    };

    uint32_t aOff = (uint32_t)((wm * 32 + (lane & 7) + ((lane >> 3) & 1) * 8) * ROWB +
                               ((lane >> 4) & 1) * 16);
    uint32_t bOff = (uint32_t)(2 * TERM +
                               (wn * 64 + (lane & 7) + ((lane >> 4) & 1) * 8) * ROWB +
                               ((lane >> 3) & 1) * 16);

    load_chunk(0);
    asm volatile("cp.async.commit_group;");

    for (int t = 0; t < NCH; t++) {
        if (t + 1 < NCH) {
            load_chunk(t + 1);
            asm volatile("cp.async.commit_group;");
            asm volatile("cp.async.wait_group 1;");
        } else {
            asm volatile("cp.async.wait_group 0;");
        }
        __syncthreads();

        uint32_t s0 = sb + (uint32_t)(t & 1) * STAGE;
#pragma unroll
        for (int ks = 0; ks < 2; ks++) {
            uint32_t ka = s0 + aOff + ks * 32;
            uint32_t kb = s0 + bOff + ks * 32;
            uint32_t ah[8], al[8], bh[16], bl[16];
            ldm4(ah, ka);
            ldm4(ah + 4, ka + 16 * ROWB);
            ldm4(al, ka + TERM);
            ldm4(al + 4, ka + TERM + 16 * ROWB);
#pragma unroll
            for (int p = 0; p < 4; p++) ldm4(bh + p * 4, kb + p * 16 * ROWB);
#pragma unroll
            for (int p = 0; p < 4; p++) ldm4(bl + p * 4, kb + TERM + p * 16 * ROWB);
#pragma unroll
            for (int mi = 0; mi < 2; mi++)
#pragma unroll
                for (int nj = 0; nj < 8; nj++) {
                    const uint32_t* fh = bh + (nj >> 1) * 4 + (nj & 1) * 2;
                    const uint32_t* fl = bl + (nj >> 1) * 4 + (nj & 1) * 2;
                    mma16816(acc[mi][nj], ah + mi * 4, fh);
                    mma16816(acc[mi][nj], al + mi * 4, fh);
                    mma16816(acc[mi][nj], ah + mi * 4, fl);
                }
        }
        __syncthreads();
    }

    // ---- epilogue ----
    int lr = lane >> 2, lc = (lane & 3) * 2;
    int g = (mBase >> 5) + wm;                      // 32-row group == warp M tile
    int mrow0 = mBase + wm * 32 + lr;
    int cBase = nBase + wn * 64 + lc;

#pragma unroll
    for (int nj = 0; nj < 8; nj++) {
        int c = cBase + nj * 8;
        float v[2][2][2];
        if (EPI == 2) {
            float2 fw = *(const float2*)(fgw + (size_t)g * 512 + c);
            float2 s2 = *(const float2*)(scv + c);
            float2 h2 = *(const float2*)(shv + c);
#pragma unroll
            for (int mi = 0; mi < 2; mi++)
#pragma unroll
                for (int h = 0; h < 2; h++) {
                    v[mi][h][0] = fmaxf(fmaf(acc[mi][nj][h * 2] + fw.x, s2.x, h2.x), 0.f);
                    v[mi][h][1] = fmaxf(fmaf(acc[mi][nj][h * 2 + 1] + fw.y, s2.y, h2.y), 0.f);
                }
        } else {
            float2 bb = *(const float2*)(bias + c);
#pragma unroll
            for (int mi = 0; mi < 2; mi++)
#pragma unroll
                for (int h = 0; h < 2; h++) {
                    v[mi][h][0] = acc[mi][nj][h * 2] + bb.x;
                    v[mi][h][1] = acc[mi][nj][h * 2 + 1] + bb.y;
                }
        }
        if (EPI != 3) {
#pragma unroll
            for (int mi = 0; mi < 2; mi++)
#pragma unroll
                for (int h = 0; h < 2; h++) {
                    int row = mrow0 + mi * 16 + h * 8;
                    *(uint32_t*)(Ch + (size_t)row * NOUT + c) =
                        bsplit_pack_hi(v[mi][h][0], v[mi][h][1]);
                    *(uint32_t*)(Cl + (size_t)row * NOUT + c) =
                        bsplit_pack_lo(v[mi][h][0], v[mi][h][1]);
                }
        }
        if (EPI != 2) {
            float m0 = fmaxf(fmaxf(v[0][0][0], v[0][1][0]), fmaxf(v[1][0][0], v[1][1][0]));
            float m1 = fmaxf(fmaxf(v[0][0][1], v[0][1][1]), fmaxf(v[1][0][1], v[1][1][1]));
#pragma unroll
            for (int o = 4; o < 32; o <<= 1) {
                m0 = fmaxf(m0, __shfl_xor_sync(0xffffffffu, m0, o));
                m1 = fmaxf(m1, __shfl_xor_sync(0xffffffffu, m1, o));
            }
            if (lane < 4) {
                aux[(size_t)g * NOUT + c] = m0;
                aux[(size_t)g * NOUT + c + 1] = m1;
            }
        }
    }
}

// -------------------- small fp32 GEMM for fgw = fg @ w3[:256] + b3 ----------
template <int EPI>
__global__ void __launch_bounds__(256) sgemm(const float* __restrict__ A,
                                             const float* __restrict__ Bm,
                                             float* __restrict__ C,
                                             float* __restrict__ aux,
                                             const float* __restrict__ bias,
                                             const float* __restrict__ scale,
                                             const float* __restrict__ shift,
                                             int M, int N, int K, int auxN) {
    __shared__ float As[2][16][132];
    __shared__ float Bs[2][16][128];

    int tid = threadIdx.x;
    int tx = tid & 15, ty = tid >> 4;
    int mBase = blockIdx.y << 7, nBase = blockIdx.x << 7;

    int aK = tid & 15, aM = tid >> 4;
    int bN = (tid & 31) << 2, bK = tid >> 5;

    const float* Ap = A + (size_t)(mBase + aM) * K + aK;
    const float* Bp = Bm + (size_t)bK * N + nBase + bN;

    float acc[8][8];
#pragma unroll
    for (int i = 0; i < 8; i++)
#pragma unroll
        for (int j = 0; j < 8; j++) acc[i][j] = 0.f;

    float ar[8];
    float4 br[2];
    int nt = K >> 4;

#pragma unroll
    for (int e = 0; e < 8; e++) ar[e] = Ap[(size_t)(e * 16) * K];
#pragma unroll
    for (int e = 0; e < 2; e++) br[e] = *(const float4*)(Bp + (size_t)(e * 8) * N);
#pragma unroll
    for (int e = 0; e < 8; e++) As[0][aK][aM + e * 16] = ar[e];
#pragma unroll
    for (int e = 0; e < 2; e++) *(float4*)&Bs[0][bK + e * 8][bN] = br[e];
    __syncthreads();

    for (int t = 0; t < nt; t++) {
        int buf = t & 1;
        if (t + 1 < nt) {
            int kOff = (t + 1) << 4;
#pragma unroll
            for (int e = 0; e < 8; e++) ar[e] = Ap[(size_t)(e * 16) * K + kOff];
#pragma unroll
            for (int e = 0; e < 2; e++)
                br[e] = *(const float4*)(Bp + (size_t)(kOff + e * 8) * N);
        }
#pragma unroll
        for (int kk = 0; kk < 16; kk++) {
            float a[8], bb[8];
            *(float4*)&a[0]  = *(const float4*)&As[buf][kk][ty * 8];
            *(float4*)&a[4]  = *(const float4*)&As[buf][kk][ty * 8 + 4];
            *(float4*)&bb[0] = *(const float4*)&Bs[buf][kk][tx * 8];
            *(float4*)&bb[4] = *(const float4*)&Bs[buf][kk][tx * 8 + 4];
#pragma unroll
            for (int i = 0; i < 8; i++)
#pragma unroll
                for (int j = 0; j < 8; j++) acc[i][j] = fmaf(a[i], bb[j], acc[i][j]);
        }
        if (t + 1 < nt) {
            int nb = buf ^ 1;
#pragma unroll
            for (int e = 0; e < 8; e++) As[nb][aK][aM + e * 16] = ar[e];
#pragma unroll
            for (int e = 0; e < 2; e++) *(float4*)&Bs[nb][bK + e * 8][bN] = br[e];
            __syncthreads();
        }
    }

    int colBase = nBase + tx * 8;
    float bb8[8];
#pragma unroll
    for (int j = 0; j < 8; j++) bb8[j] = __ldg(bias + colBase + j);
#pragma unroll
    for (int i = 0; i < 8; i++) {
#pragma unroll
        for (int j = 0; j < 8; j++) acc[i][j] += bb8[j];
        float* cp = C + (size_t)(mBase + ty * 8 + i) * N + colBase;
        *(float4*)cp = *(float4*)&acc[i][0];
        *(float4*)(cp + 4) = *(float4*)&acc[i][4];
    }
}

// ---------------------------------------------------------------------------
extern "C" void kernel_launch(void* const* d_in, const int* in_sizes, int n_in,
                              void* d_out, int out_size) {
    (void)in_sizes; (void)n_in; (void)out_size;
    const float* pcd = (const float*)d_in[0];
    const float* w1  = (const float*)d_in[2];
    const float* b1  = (const float*)d_in[3];
    const float* g1  = (const float*)d_in[4];
    const float* be1 = (const float*)d_in[5];
    const float* m1  = (const float*)d_in[6];
    const float* v1  = (const float*)d_in[7];
    const float* w2  = (const float*)d_in[8];
    const float* b2  = (const float*)d_in[9];
    const float* w3  = (const float*)d_in[10];
    const float* b3  = (const float*)d_in[11];
    const float* g2  = (const float*)d_in[12];
    const float* be2 = (const float*)d_in[13];
    const float* m2  = (const float*)d_in[14];
    const float* v2  = (const float*)d_in[15];
    const float* w4  = (const float*)d_in[16];
    const float* b4  = (const float*)d_in[17];

    float *xf, *fg, *fgw, *s1, *h1, *s2, *h2;
    __nv_bfloat16 *f1h, *f1l, *f2h, *f2l, *f3h, *f3l;
    __nv_bfloat16 *w2th, *w2tl, *w3th, *w3tl, *w4th, *w4tl;
    int* ci;
    cudaGetSymbolAddress((void**)&xf,   g_x);
    cudaGetSymbolAddress((void**)&f1h,  g_f1h);  cudaGetSymbolAddress((void**)&f1l, g_f1l);
    cudaGetSymbolAddress((void**)&f2h,  g_f2h);  cudaGetSymbolAddress((void**)&f2l, g_f2l);
    cudaGetSymbolAddress((void**)&f3h,  g_f3h);  cudaGetSymbolAddress((void**)&f3l, g_f3l);
    cudaGetSymbolAddress((void**)&w2th, g_w2th); cudaGetSymbolAddress((void**)&w2tl, g_w2tl);
    cudaGetSymbolAddress((void**)&w3th, g_w3th); cudaGetSymbolAddress((void**)&w3tl, g_w3tl);
    cudaGetSymbolAddress((void**)&w4th, g_w4th); cudaGetSymbolAddress((void**)&w4tl, g_w4tl);
    cudaGetSymbolAddress((void**)&fg,   g_fg);
    cudaGetSymbolAddress((void**)&fgw,  g_fgw);
    cudaGetSymbolAddress((void**)&ci,   g_cidx);
    cudaGetSymbolAddress((void**)&s1,   g_s1);
    cudaGetSymbolAddress((void**)&h1,   g_h1);
    cudaGetSymbolAddress((void**)&s2,   g_s2);
    cudaGetSymbolAddress((void**)&h2,   g_h2);

    constexpr int SMEM_T = 2 * STAGE;   // 81920
    cudaFuncSetAttribute(tgemm<128, 256, 1>, cudaFuncAttributeMaxDynamicSharedMemorySize, SMEM_T);
    cudaFuncSetAttribute(tgemm<256, 512, 2>, cudaFuncAttributeMaxDynamicSharedMemorySize, SMEM_T);
    cudaFuncSetAttribute(tgemm<512, 384, 3>, cudaFuncAttributeMaxDynamicSharedMemorySize, SMEM_T);

    bnprep_kernel<<<1, 512>>>(g1, be1, m1, v1, g2, be2, m2, v2, s1, h1, s2, h2);
    wprep_kernel<<<768, 256>>>(w2, w3, w4, w2th, w2tl, w3th, w3tl, w4th, w4tl);
    fps_kernel<<<32, 1024>>>(pcd, ci);
    knn_kernel<<<2048, 256>>>(pcd, ci, xf);
    layer1_kernel<<<1024, 256>>>(xf, w1, b1, s1, h1, f1h, f1l);

    // L2: f2 = f1 @ w2 + b2 ; fg = groupmax(f2)
    tgemm<128, 256, 1><<<dim3(2, 512), 256, SMEM_T>>>(
        f1h, f1l, w2th, w2tl, b2, nullptr, nullptr, nullptr, f2h, f2l, fg);
    // fgw = fg @ w3[:256] + b3   (fp32, tiny)
    sgemm<0><<<dim3(4, 16), 256>>>(fg, w3, fgw, nullptr, b3, nullptr, nullptr,
                                   2048, 512, 256, 0);
    // f3 = relu(bn2(f2 @ w3[256:] + fgw[group]))
    tgemm<256, 512, 2><<<dim3(4, 512), 256, SMEM_T>>>(
        f2h, f2l, w3th, w3tl, nullptr, fgw, s2, h2, f3h, f3l, nullptr);
    // out = groupmax(f3 @ w4 + b4)
    tgemm<512, 384, 3><<<dim3(3, 512), 256, SMEM_T>>>(
        f3h, f3l, w4th, w4tl, b4, nullptr, nullptr, nullptr, nullptr, nullptr,
        (float*)d_out);
}